// round 16
// baseline (speedup 1.0000x reference)
#include <cuda_runtime.h>
#include <cuda_fp16.h>
#include <math.h>
#include <stdint.h>

#define B_SZ   512
#define Q_SZ   16384
#define F_DIM  256
#define H_DIM  1024
#define E_DIM  512
#define D_IMG  2048
#define P_POOL 160
#define PER_NEG 32
#define N_NEAR 16
#define N_FAR  16
#define NEAR_CNT 48
#define ROWS_ALL (B_SZ + 16384)
#define IMG_SPLITS 8

__device__ float  g_gps_all[ROWS_ALL * 2];
__device__ float  g_partial[B_SZ];
__device__ float  g_logits[B_SZ * ROWS_ALL];
__device__ float  g_emb[ROWS_ALL * E_DIM];
__device__ float  g_imgpart[IMG_SPLITS * B_SZ * E_DIM];
__device__ __half g_ff_h[ROWS_ALL * (2 * F_DIM)];
__device__ __half g_h_h[ROWS_ALL * H_DIM];
__device__ __half g_emb_h[ROWS_ALL * E_DIM];
__device__ __half g_img_h[B_SZ * E_DIM];
__device__ __half g_imgs_h[B_SZ * D_IMG];
__device__ __half g_w1t_h[H_DIM * (2 * F_DIM)];
__device__ __half g_w2t_h[E_DIM * H_DIM];
__device__ __half g_wit_h[E_DIM * D_IMG];

// ===========================================================================
// helpers
// ===========================================================================
__device__ __forceinline__ uint32_t smem_u32(const void* p) {
    uint32_t a;
    asm("{ .reg .u64 t; cvta.to.shared.u64 t, %1; cvt.u32.u64 %0, t; }"
        : "=r"(a) : "l"(p));
    return a;
}
__device__ __forceinline__ void cp_async16(uint32_t dst, const void* src) {
    asm volatile("cp.async.cg.shared.global [%0], [%1], 16;" :: "r"(dst), "l"(src));
}
#define CP_COMMIT() asm volatile("cp.async.commit_group;" ::: "memory")
#define CP_WAIT0()  asm volatile("cp.async.wait_group 0;" ::: "memory")
#define CP_WAIT1()  asm volatile("cp.async.wait_group 1;" ::: "memory")

__device__ __forceinline__ void mma_f16(float* c, const uint32_t* a, const uint32_t* b) {
    asm volatile(
        "mma.sync.aligned.m16n8k16.row.col.f32.f16.f16.f32 "
        "{%0,%1,%2,%3}, {%4,%5,%6,%7}, {%8,%9}, {%0,%1,%2,%3};"
        : "+f"(c[0]), "+f"(c[1]), "+f"(c[2]), "+f"(c[3])
        : "r"(a[0]), "r"(a[1]), "r"(a[2]), "r"(a[3]), "r"(b[0]), "r"(b[1]));
}
__device__ __forceinline__ void ldmatrix_x4(uint32_t* r, uint32_t addr) {
    asm volatile("ldmatrix.sync.aligned.m8n8.x4.shared.b16 {%0,%1,%2,%3}, [%4];"
        : "=r"(r[0]), "=r"(r[1]), "=r"(r[2]), "=r"(r[3]) : "r"(addr));
}

// ===========================================================================
// selection (bit-exact, unchanged)
// ===========================================================================
__global__ void select_kernel(const float* __restrict__ gps,
                              const float* __restrict__ gallery,
                              const int* __restrict__ pool_idx,
                              const int* __restrict__ far_sel,
                              const int* __restrict__ perm) {
    const float DEG = 0.017453292519943295f;
    int b = blockIdx.x;
    int t = threadIdx.x;

    __shared__ float dsm[P_POOL];
    __shared__ float pla[P_POOL], plo[P_POOL];
    __shared__ int order[P_POOL];

    float lat1 = gps[b * 2 + 0] * DEG;
    float lon1 = gps[b * 2 + 1] * DEG;

    if (t < P_POOL) {
        int gi = pool_idx[b * P_POOL + t];
        float la = gallery[gi * 2 + 0];
        float lo = gallery[gi * 2 + 1];
        pla[t] = la; plo[t] = lo;
        float lat2 = la * DEG, lon2 = lo * DEG;
        float sdlat = sinf((lat2 - lat1) * 0.5f);
        float sdlon = sinf((lon2 - lon1) * 0.5f);
        float h = sdlat * sdlat + cosf(lat1) * cosf(lat2) * sdlon * sdlon;
        h = fminf(fmaxf(h, 0.0f), 1.0f);
        dsm[t] = 2.0f * 6371.0f * asinf(sqrtf(h));
    }
    __syncthreads();

    if (t < P_POOL) {
        float dt = dsm[t];
        int r = 0;
        #pragma unroll 8
        for (int j = 0; j < P_POOL; j++) {
            float dj = dsm[j];
            r += (dj < dt) || (dj == dt && j < t);
        }
        order[r] = t;
    }
    __syncthreads();

    if (t < PER_NEG) {
        int s = (t < N_NEAR) ? order[t]
                             : order[NEAR_CNT + far_sel[b * N_FAR + (t - N_NEAR)]];
        int q = b * PER_NEG + t;
        int pos = perm[q];
        g_gps_all[(B_SZ + pos) * 2 + 0] = pla[s];
        g_gps_all[(B_SZ + pos) * 2 + 1] = plo[s];
    }
    if (t < 2) g_gps_all[b * 2 + t] = gps[b * 2 + t];
}

__device__ __forceinline__ unsigned rotl32(unsigned x, int r) {
    return (x << r) | (x >> (32 - r));
}
__device__ __forceinline__ void threefry2x32(unsigned k0, unsigned k1,
                                             unsigned c0, unsigned c1,
                                             unsigned& o0, unsigned& o1) {
    unsigned ks[3] = { k0, k1, 0x1BD11BDAu ^ k0 ^ k1 };
    unsigned x0 = c0 + ks[0];
    unsigned x1 = c1 + ks[1];
    const int R0[4] = {13, 15, 26, 6};
    const int R1[4] = {17, 29, 16, 24};
    #pragma unroll
    for (int i = 0; i < 5; i++) {
        const int* R = (i & 1) ? R1 : R0;
        #pragma unroll
        for (int j = 0; j < 4; j++) {
            x0 += x1;
            x1 = rotl32(x1, R[j]);
            x1 ^= x0;
        }
        x0 += ks[(i + 1) % 3];
        x1 += ks[(i + 2) % 3] + (unsigned)(i + 1);
    }
    o0 = x0; o1 = x1;
}
__device__ __forceinline__ float erfinv_xla(float x) {
    float w = -log1pf(-x * x);
    float p;
    if (w < 5.0f) {
        w -= 2.5f;
        p =            2.81022636e-08f;
        p = fmaf(p, w, 3.43273939e-07f);
        p = fmaf(p, w, -3.5233877e-06f);
        p = fmaf(p, w, -4.39150654e-06f);
        p = fmaf(p, w, 0.00021858087f);
        p = fmaf(p, w, -0.00125372503f);
        p = fmaf(p, w, -0.00417768164f);
        p = fmaf(p, w, 0.246640727f);
        p = fmaf(p, w, 1.50140941f);
    } else {
        w = sqrtf(w) - 3.0f;
        p =            -0.000200214257f;
        p = fmaf(p, w, 0.000100950558f);
        p = fmaf(p, w, 0.00134934322f);
        p = fmaf(p, w, -0.00367342844f);
        p = fmaf(p, w, 0.00573950773f);
        p = fmaf(p, w, -0.0076224613f);
        p = fmaf(p, w, 0.00943887047f);
        p = fmaf(p, w, 1.00167406f);
        p = fmaf(p, w, 2.83297682f);
    }
    return p * x;
}
__device__ __forceinline__ float bits_to_normal(unsigned bits) {
    const float lo = -0.99999994f;
    float u01 = __uint_as_float((bits >> 9) | 0x3f800000u) - 1.0f;
    float v = u01 * (1.0f - lo) + lo;
    v = fmaxf(lo, v);
    return 1.4142135623730951f * erfinv_xla(v);
}

// ===========================================================================
// fourier features -> fp16, with queue-row threefry noise fused in.
// ===========================================================================
__global__ void ff_kernel(const float* __restrict__ freqs) {
    const float NOISE_STD = (float)(2500.0 / 111320.0);
    __shared__ float ns[2];
    int r = blockIdx.x;
    int j = threadIdx.x;
    if (r >= B_SZ && j < 2) {
        int e = 2 * (r - B_SZ) + j;
        unsigned o0, o1, bits;
        if (e < Q_SZ) { threefry2x32(0u, 1u, (unsigned)e, (unsigned)(e + Q_SZ), o0, o1); bits = o0; }
        else          { threefry2x32(0u, 1u, (unsigned)(e - Q_SZ), (unsigned)e, o0, o1); bits = o1; }
        ns[j] = bits_to_normal(bits) * NOISE_STD;
    }
    if (r >= B_SZ) __syncthreads();
    float lat = g_gps_all[r * 2 + 0];
    float lon = g_gps_all[r * 2 + 1];
    if (r >= B_SZ) { lat += ns[0]; lon += ns[1]; }
    float ang = lat * freqs[j] + lon * freqs[F_DIM + j];
    float s, c;
    __sincosf(ang, &s, &c);
    g_ff_h[r * (2 * F_DIM) + j]         = __float2half_rn(s);
    g_ff_h[r * (2 * F_DIM) + F_DIM + j] = __float2half_rn(c);
}

// ===========================================================================
// One launch: all 3 weight transposes (f32 -> fp16 [N,K]) + imgs rounding.
// ===========================================================================
__device__ __forceinline__ void tr_block(const float* __restrict__ in,
                                         __half* __restrict__ out,
                                         int K, int N, int k0, int n0, int tid) {
    __shared__ float tile[32][33];
    int tx = tid & 31, ty = tid >> 5;
    #pragma unroll
    for (int i = 0; i < 32; i += 8)
        tile[ty + i][tx] = in[(size_t)(k0 + ty + i) * N + n0 + tx];
    __syncthreads();
    #pragma unroll
    for (int i = 0; i < 32; i += 8)
        out[(size_t)(n0 + ty + i) * K + k0 + tx] = __float2half_rn(tile[tx][ty + i]);
}

__global__ void prep_kernel(const float* __restrict__ W1,
                            const float* __restrict__ W2,
                            const float* __restrict__ Wimg,
                            const float* __restrict__ imgs) {
    int b = blockIdx.x;
    int tid = threadIdx.x;
    if (b < 512) {
        tr_block(W1, g_w1t_h, 2 * F_DIM, H_DIM, (b >> 5) * 32, (b & 31) * 32, tid);
    } else if (b < 1024) {
        int c = b - 512;
        tr_block(W2, g_w2t_h, H_DIM, E_DIM, (c >> 4) * 32, (c & 15) * 32, tid);
    } else if (b < 2048) {
        int c = b - 1024;
        tr_block(Wimg, g_wit_h, D_IMG, E_DIM, (c >> 4) * 32, (c & 15) * 32, tid);
    } else {
        int c = b - 2048;
        int base = c * 1024 + tid;
        #pragma unroll
        for (int k = 0; k < 4; k++)
            g_imgs_h[base + k * 256] = __float2half_rn(imgs[base + k * 256]);
    }
}

// ===========================================================================
// gemm_h: proven 128x128 config (round 12). BK=64, 2-stage cp.async.
//   C[M,N] = A[M,K] @ B[N,K]^T
// EPI: 0 none(f32), 1 bias+relu(fp16), 2 bias(f32)
// ===========================================================================
#define GSTH 72
#define TILEH (128 * GSTH)
#define GEMM_SMEM (4 * TILEH * 2 + 512)

template<int EPI, typename OT>
__global__ void __launch_bounds__(256, 2)
gemm_h(const __half* __restrict__ A, const __half* __restrict__ Bm,
       OT* __restrict__ C, const float* __restrict__ bias,
       int M, int N, int K, int lda, int ldb) {
    extern __shared__ __half smh[];
    float* biass = (float*)(smh + 4 * TILEH);

    const int tid  = threadIdx.x;
    const int wid  = tid >> 5;
    const int lane = tid & 31;
    const int gid  = lane >> 2;
    const int tid4 = lane & 3;
    const int wm   = (wid & 1) * 64;
    const int wn   = (wid >> 1) * 32;
    const int bm   = blockIdx.y * 128;
    const int bn   = blockIdx.x * 128;
    const size_t koff = (size_t)blockIdx.z * K;
    if (blockIdx.z) C += (size_t)blockIdx.z * M * N;

    if ((EPI == 1 || EPI == 2) && tid < 128) biass[tid] = bias[bn + tid];

    const uint32_t sbase = smem_u32(smh);
    const int c_row = tid >> 3;
    const int c_off = (tid & 7) * 8;

    auto prefetch = [&](int s, int buf) {
        const int kc = s * 64;
        const uint32_t ad = sbase + (buf * TILEH) * 2;
        const uint32_t bd = sbase + ((2 + buf) * TILEH) * 2;
        #pragma unroll
        for (int it = 0; it < 4; it++) {
            int row = it * 32 + c_row;
            cp_async16(ad + (row * GSTH + c_off) * 2,
                       &A[(size_t)(bm + row) * lda + koff + kc + c_off]);
            cp_async16(bd + (row * GSTH + c_off) * 2,
                       &Bm[(size_t)(bn + row) * ldb + koff + kc + c_off]);
        }
        CP_COMMIT();
    };

    const int lane7 = lane & 7;
    const int a_row = wm + lane7 + ((lane >> 3) & 1) * 8;
    const int a_kh  = ((lane >> 4) & 1) * 8;
    const uint32_t a_lm = sbase + (a_row * GSTH + a_kh) * 2;
    const int b_row = wn + lane7 + ((lane >> 4) & 1) * 8;
    const int b_kh  = ((lane >> 3) & 1) * 8;
    const uint32_t b_lm = sbase + 2 * TILEH * 2 + (b_row * GSTH + b_kh) * 2;

    float acc[4][4][4];
    #pragma unroll
    for (int mi = 0; mi < 4; mi++)
        #pragma unroll
        for (int ni = 0; ni < 4; ni++)
            #pragma unroll
            for (int j = 0; j < 4; j++) acc[mi][ni][j] = 0.0f;

    const int nst = K >> 6;
    prefetch(0, 0);
    if (nst > 1) prefetch(1, 1);

    for (int s = 0; s < nst; s++) {
        const int buf = s & 1;
        if (s < nst - 1) CP_WAIT1(); else CP_WAIT0();
        __syncthreads();

        const uint32_t boff = buf * (TILEH * 2);
        #pragma unroll
        for (int kc16 = 0; kc16 < 4; kc16++) {
            const uint32_t kb = kc16 * 32;
            uint32_t a[4][4], b[4][2];
            #pragma unroll
            for (int mi = 0; mi < 4; mi++)
                ldmatrix_x4(a[mi], a_lm + boff + mi * (16 * GSTH * 2) + kb);
            #pragma unroll
            for (int nj = 0; nj < 2; nj++) {
                uint32_t r[4];
                ldmatrix_x4(r, b_lm + boff + nj * (16 * GSTH * 2) + kb);
                b[2 * nj][0] = r[0]; b[2 * nj][1] = r[1];
                b[2 * nj + 1][0] = r[2]; b[2 * nj + 1][1] = r[3];
            }
            #pragma unroll
            for (int mi = 0; mi < 4; mi++)
                #pragma unroll
                for (int ni = 0; ni < 4; ni++)
                    mma_f16(acc[mi][ni], a[mi], b[ni]);
        }

        __syncthreads();
        if (s + 2 < nst) prefetch(s + 2, buf);
    }

    #pragma unroll
    for (int mi = 0; mi < 4; mi++) {
        int r0 = bm + wm + mi * 16 + gid;
        #pragma unroll
        for (int ni = 0; ni < 4; ni++) {
            int coll = wn + ni * 8 + tid4 * 2;
            int col = bn + coll;
            float v0 = acc[mi][ni][0], v1 = acc[mi][ni][1];
            float v2 = acc[mi][ni][2], v3 = acc[mi][ni][3];
            if (EPI == 1 || EPI == 2) {
                float b0 = biass[coll], b1 = biass[coll + 1];
                v0 += b0; v1 += b1; v2 += b0; v3 += b1;
                if (EPI == 1) {
                    v0 = fmaxf(v0, 0.0f); v1 = fmaxf(v1, 0.0f);
                    v2 = fmaxf(v2, 0.0f); v3 = fmaxf(v3, 0.0f);
                }
            }
            if constexpr (sizeof(OT) == 2) {
                __half2 p01, p23;
                p01.x = __float2half_rn(v0); p01.y = __float2half_rn(v1);
                p23.x = __float2half_rn(v2); p23.y = __float2half_rn(v3);
                *(__half2*)&C[(size_t)r0 * N + col] = p01;
                *(__half2*)&C[(size_t)(r0 + 8) * N + col] = p23;
            } else {
                float2 p01 = { v0, v1 };
                float2 p23 = { v2, v3 };
                *(float2*)&C[(size_t)r0 * N + col] = p01;
                *(float2*)&C[(size_t)(r0 + 8) * N + col] = p23;
            }
        }
    }
}

// ===========================================================================
// gemm_s: small-tile variant for GEMM1. BM=128, BN=64, warp tile 32x32
// (4m x 2n warps), BK=64, 2-stage, 3 CTAs/SM. Output fp16 bias+relu.
// ===========================================================================
#define ATILE_S (128 * GSTH)          // halves
#define BTILE_S (64 * GSTH)
#define SMEM_S  ((2 * ATILE_S + 2 * BTILE_S) * 2 + 512)

__global__ void __launch_bounds__(256, 3)
gemm_s(const __half* __restrict__ A, const __half* __restrict__ Bm,
       __half* __restrict__ C, const float* __restrict__ bias,
       int M, int N, int K) {
    extern __shared__ __half smh[];
    float* biass = (float*)(smh + 2 * ATILE_S + 2 * BTILE_S);

    const int tid  = threadIdx.x;
    const int wid  = tid >> 5;
    const int lane = tid & 31;
    const int gid  = lane >> 2;
    const int tid4 = lane & 3;
    const int wm   = (wid & 3) * 32;     // 4 m-warps
    const int wn   = (wid >> 2) * 32;    // 2 n-warps
    const int bm   = blockIdx.y * 128;
    const int bn   = blockIdx.x * 64;

    if (tid < 64) biass[tid] = bias[bn + tid];

    const uint32_t sbase = smem_u32(smh);
    const uint32_t bbase = sbase + 2 * ATILE_S * 2;
    const int c_row = tid >> 3;
    const int c_off = (tid & 7) * 8;

    auto prefetch = [&](int s, int buf) {
        const int kc = s * 64;
        const uint32_t ad = sbase + (buf * ATILE_S) * 2;
        const uint32_t bd = bbase + (buf * BTILE_S) * 2;
        #pragma unroll
        for (int it = 0; it < 4; it++) {
            int row = it * 32 + c_row;
            cp_async16(ad + (row * GSTH + c_off) * 2,
                       &A[(size_t)(bm + row) * K + kc + c_off]);
        }
        #pragma unroll
        for (int it = 0; it < 2; it++) {
            int row = it * 32 + c_row;
            cp_async16(bd + (row * GSTH + c_off) * 2,
                       &Bm[(size_t)(bn + row) * K + kc + c_off]);
        }
        CP_COMMIT();
    };

    const int lane7 = lane & 7;
    const int a_row = wm + lane7 + ((lane >> 3) & 1) * 8;
    const int a_kh  = ((lane >> 4) & 1) * 8;
    const uint32_t a_lm = sbase + (a_row * GSTH + a_kh) * 2;
    const int b_row = wn + lane7 + ((lane >> 4) & 1) * 8;
    const int b_kh  = ((lane >> 3) & 1) * 8;
    const uint32_t b_lm = bbase + (b_row * GSTH + b_kh) * 2;

    float acc[2][4][4];
    #pragma unroll
    for (int mi = 0; mi < 2; mi++)
        #pragma unroll
        for (int ni = 0; ni < 4; ni++)
            #pragma unroll
            for (int j = 0; j < 4; j++) acc[mi][ni][j] = 0.0f;

    const int nst = K >> 6;
    prefetch(0, 0);
    if (nst > 1) prefetch(1, 1);

    for (int s = 0; s < nst; s++) {
        const int buf = s & 1;
        if (s < nst - 1) CP_WAIT1(); else CP_WAIT0();
        __syncthreads();

        const uint32_t aoff = buf * (ATILE_S * 2);
        const uint32_t boff = buf * (BTILE_S * 2);
        #pragma unroll
        for (int kc16 = 0; kc16 < 4; kc16++) {
            const uint32_t kb = kc16 * 32;
            uint32_t a[2][4], b[4][2];
            #pragma unroll
            for (int mi = 0; mi < 2; mi++)
                ldmatrix_x4(a[mi], a_lm + aoff + mi * (16 * GSTH * 2) + kb);
            #pragma unroll
            for (int nj = 0; nj < 2; nj++) {
                uint32_t r[4];
                ldmatrix_x4(r, b_lm + boff + nj * (16 * GSTH * 2) + kb);
                b[2 * nj][0] = r[0]; b[2 * nj][1] = r[1];
                b[2 * nj + 1][0] = r[2]; b[2 * nj + 1][1] = r[3];
            }
            #pragma unroll
            for (int mi = 0; mi < 2; mi++)
                #pragma unroll
                for (int ni = 0; ni < 4; ni++)
                    mma_f16(acc[mi][ni], a[mi], b[ni]);
        }

        __syncthreads();
        if (s + 2 < nst) prefetch(s + 2, buf);
    }

    #pragma unroll
    for (int mi = 0; mi < 2; mi++) {
        int r0 = bm + wm + mi * 16 + gid;
        #pragma unroll
        for (int ni = 0; ni < 4; ni++) {
            int coll = wn + ni * 8 + tid4 * 2;
            int col = bn + coll;
            float v0 = acc[mi][ni][0] + biass[coll];
            float v1 = acc[mi][ni][1] + biass[coll + 1];
            float v2 = acc[mi][ni][2] + biass[coll];
            float v3 = acc[mi][ni][3] + biass[coll + 1];
            v0 = fmaxf(v0, 0.0f); v1 = fmaxf(v1, 0.0f);
            v2 = fmaxf(v2, 0.0f); v3 = fmaxf(v3, 0.0f);
            __half2 p01, p23;
            p01.x = __float2half_rn(v0); p01.y = __float2half_rn(v1);
            p23.x = __float2half_rn(v2); p23.y = __float2half_rn(v3);
            *(__half2*)&C[(size_t)r0 * N + col] = p01;
            *(__half2*)&C[(size_t)(r0 + 8) * N + col] = p23;
        }
    }
}

// ===========================================================================
__global__ void l2norm_half(const float* __restrict__ X, __half* __restrict__ Y) {
    int r = blockIdx.x;
    int t = threadIdx.x;
    const float* row = X + (size_t)r * 512;
    float a = row[t], b = row[t + 256];
    float s = a * a + b * b;
    __shared__ float sm[256];
    sm[t] = s;
    __syncthreads();
    for (int o = 128; o > 0; o >>= 1) {
        if (t < o) sm[t] += sm[t + o];
        __syncthreads();
    }
    float inv = 1.0f / sqrtf(sm[0]);
    Y[(size_t)r * 512 + t]       = __float2half_rn(a * inv);
    Y[(size_t)r * 512 + t + 256] = __float2half_rn(b * inv);
}

__global__ void l2norm_img(__half* __restrict__ Y) {
    int r = blockIdx.x;
    int t = threadIdx.x;
    float a = 0.0f, b = 0.0f;
    #pragma unroll
    for (int z = 0; z < IMG_SPLITS; z++) {
        const float* p = g_imgpart + (size_t)z * B_SZ * E_DIM + (size_t)r * 512;
        a += p[t];
        b += p[t + 256];
    }
    float s = a * a + b * b;
    __shared__ float sm[256];
    sm[t] = s;
    __syncthreads();
    for (int o = 128; o > 0; o >>= 1) {
        if (t < o) sm[t] += sm[t + o];
        __syncthreads();
    }
    float inv = 1.0f / sqrtf(sm[0]);
    Y[(size_t)r * 512 + t]       = __float2half_rn(a * inv);
    Y[(size_t)r * 512 + t + 256] = __float2half_rn(b * inv);
}

// ===========================================================================
// lse, single pass (fixed exact shift m = s; |logits| <= 1)
// ===========================================================================
__global__ void lse_kernel(const float* __restrict__ scale_ptr) {
    int r = blockIdx.x;
    int t = threadIdx.x;
    float s = scale_ptr[0];
    const float4* row4 = (const float4*)(g_logits + (size_t)r * ROWS_ALL);
    const int n4 = ROWS_ALL / 4;

    float sum = 0.0f;
    for (int j = t; j < n4; j += 256) {
        float4 v = row4[j];
        sum += expf(fmaf(s, v.x, -s)) + expf(fmaf(s, v.y, -s))
             + expf(fmaf(s, v.z, -s)) + expf(fmaf(s, v.w, -s));
    }
    __shared__ float sm[256];
    sm[t] = sum;
    __syncthreads();
    for (int o = 128; o > 0; o >>= 1) {
        if (t < o) sm[t] += sm[t + o];
        __syncthreads();
    }
    if (t == 0) {
        float diag = g_logits[(size_t)r * ROWS_ALL + r];
        g_partial[r] = fmaf(s, diag, -s) - logf(sm[0]);
    }
}

__global__ void final_kernel(float* __restrict__ out) {
    int t = threadIdx.x;
    __shared__ float sm[512];
    sm[t] = g_partial[t];
    __syncthreads();
    for (int o = 256; o > 0; o >>= 1) {
        if (t < o) sm[t] += sm[t + o];
        __syncthreads();
    }
    if (t == 0) out[0] = -sm[0] / (float)B_SZ;
}

// ===========================================================================
extern "C" void kernel_launch(void* const* d_in, const int* in_sizes, int n_in,
                              void* d_out, int out_size) {
    const float* imgs        = (const float*)d_in[0];
    const float* gps         = (const float*)d_in[1];
    const float* gallery     = (const float*)d_in[3];
    const float* W_img       = (const float*)d_in[4];
    const float* freqs       = (const float*)d_in[5];
    const float* W1          = (const float*)d_in[6];
    const float* b1          = (const float*)d_in[7];
    const float* W2          = (const float*)d_in[8];
    const float* b2          = (const float*)d_in[9];
    const float* logit_scale = (const float*)d_in[10];
    const int*   pool_idx    = (const int*)d_in[11];
    const int*   far_sel     = (const int*)d_in[12];
    const int*   perm        = (const int*)d_in[13];
    float* out = (float*)d_out;

    void *p_ffh, *p_hh, *p_emb, *p_embh, *p_imgh, *p_imgsh;
    void *p_w1t, *p_w2t, *p_wit, *p_logits, *p_part;
    cudaGetSymbolAddress(&p_ffh, g_ff_h);
    cudaGetSymbolAddress(&p_hh, g_h_h);
    cudaGetSymbolAddress(&p_emb, g_emb);
    cudaGetSymbolAddress(&p_embh, g_emb_h);
    cudaGetSymbolAddress(&p_imgh, g_img_h);
    cudaGetSymbolAddress(&p_imgsh, g_imgs_h);
    cudaGetSymbolAddress(&p_w1t, g_w1t_h);
    cudaGetSymbolAddress(&p_w2t, g_w2t_h);
    cudaGetSymbolAddress(&p_wit, g_wit_h);
    cudaGetSymbolAddress(&p_logits, g_logits);
    cudaGetSymbolAddress(&p_part, g_imgpart);
    __half* ffh  = (__half*)p_ffh;
    __half* hh   = (__half*)p_hh;
    float*  embp = (float*)p_emb;
    __half* embh = (__half*)p_embh;
    __half* imgh = (__half*)p_imgh;
    __half* w1t  = (__half*)p_w1t;
    __half* w2t  = (__half*)p_w2t;
    __half* wit  = (__half*)p_wit;
    float*  partp= (float*)p_part;

    cudaFuncSetAttribute(gemm_h<0, float>,  cudaFuncAttributeMaxDynamicSharedMemorySize, GEMM_SMEM);
    cudaFuncSetAttribute(gemm_h<2, float>,  cudaFuncAttributeMaxDynamicSharedMemorySize, GEMM_SMEM);
    cudaFuncSetAttribute(gemm_s, cudaFuncAttributeMaxDynamicSharedMemorySize, SMEM_S);

    select_kernel<<<B_SZ, 192>>>(gps, gallery, pool_idx, far_sel, perm);
    ff_kernel<<<ROWS_ALL, 256>>>(freqs);
    prep_kernel<<<3072, 256>>>(W1, W2, W_img, imgs);

    // h = relu(ff @ W1 + b1) -> fp16     K=512, small-tile 3-CTA/SM variant
    gemm_s<<<dim3(H_DIM / 64, ROWS_ALL / 128), 256, SMEM_S>>>(
        ffh, w1t, hh, b1, ROWS_ALL, H_DIM, 2 * F_DIM);
    // emb = h @ W2 + b2 -> f32           K=1024
    gemm_h<2, float><<<dim3(E_DIM / 128, ROWS_ALL / 128, 1), 256, GEMM_SMEM>>>(
        hh, w2t, embp, b2, ROWS_ALL, E_DIM, H_DIM, H_DIM, H_DIM);
    l2norm_half<<<ROWS_ALL, 256>>>(embp, embh);

    // img_emb partials: split-K x8       K=256 each
    gemm_h<0, float><<<dim3(E_DIM / 128, B_SZ / 128, IMG_SPLITS), 256, GEMM_SMEM>>>(
        (__half*)p_imgsh, wit, partp, nullptr, B_SZ, E_DIM, D_IMG / IMG_SPLITS, D_IMG, D_IMG);
    l2norm_img<<<B_SZ, 256>>>(imgh);

    // logits = img_emb @ emb^T -> f32    K=512
    gemm_h<0, float><<<dim3(ROWS_ALL / 128, B_SZ / 128, 1), 256, GEMM_SMEM>>>(
        imgh, embh, (float*)p_logits, nullptr, B_SZ, ROWS_ALL, E_DIM, E_DIM, E_DIM);

    lse_kernel<<<B_SZ, 256>>>(logit_scale);
    final_kernel<<<1, B_SZ>>>(out);
}

// round 17
// speedup vs baseline: 1.0393x; 1.0393x over previous
#include <cuda_runtime.h>
#include <cuda_fp16.h>
#include <math.h>
#include <stdint.h>

#define B_SZ   512
#define Q_SZ   16384
#define F_DIM  256
#define H_DIM  1024
#define E_DIM  512
#define D_IMG  2048
#define P_POOL 160
#define PER_NEG 32
#define N_NEAR 16
#define N_FAR  16
#define NEAR_CNT 48
#define ROWS_ALL (B_SZ + 16384)
#define IMG_SPLITS 8

__device__ float  g_gps_all[ROWS_ALL * 2];
__device__ float  g_partial[B_SZ];
__device__ float  g_logits[B_SZ * ROWS_ALL];
__device__ float  g_emb[ROWS_ALL * E_DIM];
__device__ float  g_imgpart[IMG_SPLITS * B_SZ * E_DIM];
__device__ __half g_ff_h[ROWS_ALL * (2 * F_DIM)];
__device__ __half g_h_h[ROWS_ALL * H_DIM];
__device__ __half g_emb_h[ROWS_ALL * E_DIM];
__device__ __half g_img_h[B_SZ * E_DIM];
__device__ __half g_imgs_h[B_SZ * D_IMG];
__device__ __half g_w1t_h[H_DIM * (2 * F_DIM)];
__device__ __half g_w2t_h[E_DIM * H_DIM];
__device__ __half g_wit_h[E_DIM * D_IMG];

// ===========================================================================
// helpers
// ===========================================================================
__device__ __forceinline__ uint32_t smem_u32(const void* p) {
    uint32_t a;
    asm("{ .reg .u64 t; cvta.to.shared.u64 t, %1; cvt.u32.u64 %0, t; }"
        : "=r"(a) : "l"(p));
    return a;
}
__device__ __forceinline__ void cp_async16(uint32_t dst, const void* src) {
    asm volatile("cp.async.cg.shared.global [%0], [%1], 16;" :: "r"(dst), "l"(src));
}
#define CP_COMMIT() asm volatile("cp.async.commit_group;" ::: "memory")
#define CP_WAIT0()  asm volatile("cp.async.wait_group 0;" ::: "memory")
#define CP_WAIT1()  asm volatile("cp.async.wait_group 1;" ::: "memory")

__device__ __forceinline__ void mma_f16(float* c, const uint32_t* a, const uint32_t* b) {
    asm volatile(
        "mma.sync.aligned.m16n8k16.row.col.f32.f16.f16.f32 "
        "{%0,%1,%2,%3}, {%4,%5,%6,%7}, {%8,%9}, {%0,%1,%2,%3};"
        : "+f"(c[0]), "+f"(c[1]), "+f"(c[2]), "+f"(c[3])
        : "r"(a[0]), "r"(a[1]), "r"(a[2]), "r"(a[3]), "r"(b[0]), "r"(b[1]));
}
__device__ __forceinline__ void ldmatrix_x4(uint32_t* r, uint32_t addr) {
    asm volatile("ldmatrix.sync.aligned.m8n8.x4.shared.b16 {%0,%1,%2,%3}, [%4];"
        : "=r"(r[0]), "=r"(r[1]), "=r"(r[2]), "=r"(r[3]) : "r"(addr));
}

// ===========================================================================
// selection (bit-exact, unchanged)
// ===========================================================================
__global__ void select_kernel(const float* __restrict__ gps,
                              const float* __restrict__ gallery,
                              const int* __restrict__ pool_idx,
                              const int* __restrict__ far_sel,
                              const int* __restrict__ perm) {
    const float DEG = 0.017453292519943295f;
    int b = blockIdx.x;
    int t = threadIdx.x;

    __shared__ float dsm[P_POOL];
    __shared__ float pla[P_POOL], plo[P_POOL];
    __shared__ int order[P_POOL];

    float lat1 = gps[b * 2 + 0] * DEG;
    float lon1 = gps[b * 2 + 1] * DEG;

    if (t < P_POOL) {
        int gi = pool_idx[b * P_POOL + t];
        float la = gallery[gi * 2 + 0];
        float lo = gallery[gi * 2 + 1];
        pla[t] = la; plo[t] = lo;
        float lat2 = la * DEG, lon2 = lo * DEG;
        float sdlat = sinf((lat2 - lat1) * 0.5f);
        float sdlon = sinf((lon2 - lon1) * 0.5f);
        float h = sdlat * sdlat + cosf(lat1) * cosf(lat2) * sdlon * sdlon;
        h = fminf(fmaxf(h, 0.0f), 1.0f);
        dsm[t] = 2.0f * 6371.0f * asinf(sqrtf(h));
    }
    __syncthreads();

    if (t < P_POOL) {
        float dt = dsm[t];
        int r = 0;
        #pragma unroll 8
        for (int j = 0; j < P_POOL; j++) {
            float dj = dsm[j];
            r += (dj < dt) || (dj == dt && j < t);
        }
        order[r] = t;
    }
    __syncthreads();

    if (t < PER_NEG) {
        int s = (t < N_NEAR) ? order[t]
                             : order[NEAR_CNT + far_sel[b * N_FAR + (t - N_NEAR)]];
        int q = b * PER_NEG + t;
        int pos = perm[q];
        g_gps_all[(B_SZ + pos) * 2 + 0] = pla[s];
        g_gps_all[(B_SZ + pos) * 2 + 1] = plo[s];
    }
    if (t < 2) g_gps_all[b * 2 + t] = gps[b * 2 + t];
}

__device__ __forceinline__ unsigned rotl32(unsigned x, int r) {
    return (x << r) | (x >> (32 - r));
}
__device__ __forceinline__ void threefry2x32(unsigned k0, unsigned k1,
                                             unsigned c0, unsigned c1,
                                             unsigned& o0, unsigned& o1) {
    unsigned ks[3] = { k0, k1, 0x1BD11BDAu ^ k0 ^ k1 };
    unsigned x0 = c0 + ks[0];
    unsigned x1 = c1 + ks[1];
    const int R0[4] = {13, 15, 26, 6};
    const int R1[4] = {17, 29, 16, 24};
    #pragma unroll
    for (int i = 0; i < 5; i++) {
        const int* R = (i & 1) ? R1 : R0;
        #pragma unroll
        for (int j = 0; j < 4; j++) {
            x0 += x1;
            x1 = rotl32(x1, R[j]);
            x1 ^= x0;
        }
        x0 += ks[(i + 1) % 3];
        x1 += ks[(i + 2) % 3] + (unsigned)(i + 1);
    }
    o0 = x0; o1 = x1;
}
__device__ __forceinline__ float erfinv_xla(float x) {
    float w = -log1pf(-x * x);
    float p;
    if (w < 5.0f) {
        w -= 2.5f;
        p =            2.81022636e-08f;
        p = fmaf(p, w, 3.43273939e-07f);
        p = fmaf(p, w, -3.5233877e-06f);
        p = fmaf(p, w, -4.39150654e-06f);
        p = fmaf(p, w, 0.00021858087f);
        p = fmaf(p, w, -0.00125372503f);
        p = fmaf(p, w, -0.00417768164f);
        p = fmaf(p, w, 0.246640727f);
        p = fmaf(p, w, 1.50140941f);
    } else {
        w = sqrtf(w) - 3.0f;
        p =            -0.000200214257f;
        p = fmaf(p, w, 0.000100950558f);
        p = fmaf(p, w, 0.00134934322f);
        p = fmaf(p, w, -0.00367342844f);
        p = fmaf(p, w, 0.00573950773f);
        p = fmaf(p, w, -0.0076224613f);
        p = fmaf(p, w, 0.00943887047f);
        p = fmaf(p, w, 1.00167406f);
        p = fmaf(p, w, 2.83297682f);
    }
    return p * x;
}
__device__ __forceinline__ float bits_to_normal(unsigned bits) {
    const float lo = -0.99999994f;
    float u01 = __uint_as_float((bits >> 9) | 0x3f800000u) - 1.0f;
    float v = u01 * (1.0f - lo) + lo;
    v = fmaxf(lo, v);
    return 1.4142135623730951f * erfinv_xla(v);
}

// ===========================================================================
// fourier features -> fp16, with queue-row threefry noise fused in.
// ===========================================================================
__global__ void ff_kernel(const float* __restrict__ freqs) {
    const float NOISE_STD = (float)(2500.0 / 111320.0);
    __shared__ float ns[2];
    int r = blockIdx.x;
    int j = threadIdx.x;
    if (r >= B_SZ && j < 2) {
        int e = 2 * (r - B_SZ) + j;
        unsigned o0, o1, bits;
        if (e < Q_SZ) { threefry2x32(0u, 1u, (unsigned)e, (unsigned)(e + Q_SZ), o0, o1); bits = o0; }
        else          { threefry2x32(0u, 1u, (unsigned)(e - Q_SZ), (unsigned)e, o0, o1); bits = o1; }
        ns[j] = bits_to_normal(bits) * NOISE_STD;
    }
    if (r >= B_SZ) __syncthreads();
    float lat = g_gps_all[r * 2 + 0];
    float lon = g_gps_all[r * 2 + 1];
    if (r >= B_SZ) { lat += ns[0]; lon += ns[1]; }
    float ang = lat * freqs[j] + lon * freqs[F_DIM + j];
    float s, c;
    __sincosf(ang, &s, &c);
    g_ff_h[r * (2 * F_DIM) + j]         = __float2half_rn(s);
    g_ff_h[r * (2 * F_DIM) + F_DIM + j] = __float2half_rn(c);
}

// ===========================================================================
// One launch: all 3 weight transposes (f32 -> fp16 [N,K]) + imgs rounding.
// ===========================================================================
__device__ __forceinline__ void tr_block(const float* __restrict__ in,
                                         __half* __restrict__ out,
                                         int K, int N, int k0, int n0, int tid) {
    __shared__ float tile[32][33];
    int tx = tid & 31, ty = tid >> 5;
    #pragma unroll
    for (int i = 0; i < 32; i += 8)
        tile[ty + i][tx] = in[(size_t)(k0 + ty + i) * N + n0 + tx];
    __syncthreads();
    #pragma unroll
    for (int i = 0; i < 32; i += 8)
        out[(size_t)(n0 + ty + i) * K + k0 + tx] = __float2half_rn(tile[tx][ty + i]);
}

__global__ void prep_kernel(const float* __restrict__ W1,
                            const float* __restrict__ W2,
                            const float* __restrict__ Wimg,
                            const float* __restrict__ imgs) {
    int b = blockIdx.x;
    int tid = threadIdx.x;
    if (b < 512) {
        tr_block(W1, g_w1t_h, 2 * F_DIM, H_DIM, (b >> 5) * 32, (b & 31) * 32, tid);
    } else if (b < 1024) {
        int c = b - 512;
        tr_block(W2, g_w2t_h, H_DIM, E_DIM, (c >> 4) * 32, (c & 15) * 32, tid);
    } else if (b < 2048) {
        int c = b - 1024;
        tr_block(Wimg, g_wit_h, D_IMG, E_DIM, (c >> 4) * 32, (c & 15) * 32, tid);
    } else {
        int c = b - 2048;
        int base = c * 1024 + tid;
        #pragma unroll
        for (int k = 0; k < 4; k++)
            g_imgs_h[base + k * 256] = __float2half_rn(imgs[base + k * 256]);
    }
}

// ===========================================================================
// fp16 tensor-core GEMM: BK=64, 3-stage cp.async, ONE barrier per stage.
//   C[M,N] = A[M,K] @ B[N,K]^T
// Schedule per iter s: wait(stage s) -> bar -> prefetch(s+2 into (s+2)%3)
//                      -> compute (s%3). Prefetch target held stage s-1,
//                      freed by this iteration's barrier.
// EPI: 0 none(f32), 1 bias+relu(fp16), 2 bias(f32)
// ===========================================================================
#define GSTH 72
#define TILEH (128 * GSTH)
#define NSTG 3
#define GEMM_SMEM (2 * NSTG * TILEH * 2 + 512)

template<int EPI, typename OT>
__global__ void __launch_bounds__(256, 2)
gemm_h(const __half* __restrict__ A, const __half* __restrict__ Bm,
       OT* __restrict__ C, const float* __restrict__ bias,
       int M, int N, int K, int lda, int ldb) {
    extern __shared__ __half smh[];
    float* biass = (float*)(smh + 2 * NSTG * TILEH);

    const int tid  = threadIdx.x;
    const int wid  = tid >> 5;
    const int lane = tid & 31;
    const int gid  = lane >> 2;
    const int tid4 = lane & 3;
    const int wm   = (wid & 1) * 64;
    const int wn   = (wid >> 1) * 32;
    const int bm   = blockIdx.y * 128;
    const int bn   = blockIdx.x * 128;
    const size_t koff = (size_t)blockIdx.z * K;
    if (blockIdx.z) C += (size_t)blockIdx.z * M * N;

    if ((EPI == 1 || EPI == 2) && tid < 128) biass[tid] = bias[bn + tid];

    const uint32_t sbase = smem_u32(smh);
    const int c_row = tid >> 3;
    const int c_off = (tid & 7) * 8;

    auto prefetch = [&](int s, int buf) {
        const int kc = s * 64;
        const uint32_t ad = sbase + (buf * TILEH) * 2;
        const uint32_t bd = sbase + ((NSTG + buf) * TILEH) * 2;
        #pragma unroll
        for (int it = 0; it < 4; it++) {
            int row = it * 32 + c_row;
            cp_async16(ad + (row * GSTH + c_off) * 2,
                       &A[(size_t)(bm + row) * lda + koff + kc + c_off]);
            cp_async16(bd + (row * GSTH + c_off) * 2,
                       &Bm[(size_t)(bn + row) * ldb + koff + kc + c_off]);
        }
        CP_COMMIT();
    };

    const int lane7 = lane & 7;
    const int a_row = wm + lane7 + ((lane >> 3) & 1) * 8;
    const int a_kh  = ((lane >> 4) & 1) * 8;
    const uint32_t a_lm = sbase + (a_row * GSTH + a_kh) * 2;
    const int b_row = wn + lane7 + ((lane >> 4) & 1) * 8;
    const int b_kh  = ((lane >> 3) & 1) * 8;
    const uint32_t b_lm = sbase + NSTG * TILEH * 2 + (b_row * GSTH + b_kh) * 2;

    float acc[4][4][4];
    #pragma unroll
    for (int mi = 0; mi < 4; mi++)
        #pragma unroll
        for (int ni = 0; ni < 4; ni++)
            #pragma unroll
            for (int j = 0; j < 4; j++) acc[mi][ni][j] = 0.0f;

    const int nst = K >> 6;   // >= 2 at all call sites
    prefetch(0, 0);
    if (nst > 1) prefetch(1, 1);

    int buf = 0;          // s % 3
    int pbuf = 2;         // (s+2) % 3
    for (int s = 0; s < nst; s++) {
        if (s < nst - 1) CP_WAIT1(); else CP_WAIT0();
        __syncthreads();

        if (s + 2 < nst) prefetch(s + 2, pbuf);

        const uint32_t boff = buf * (TILEH * 2);
        #pragma unroll
        for (int kc16 = 0; kc16 < 4; kc16++) {
            const uint32_t kb = kc16 * 32;
            uint32_t a[4][4], b[4][2];
            #pragma unroll
            for (int mi = 0; mi < 4; mi++)
                ldmatrix_x4(a[mi], a_lm + boff + mi * (16 * GSTH * 2) + kb);
            #pragma unroll
            for (int nj = 0; nj < 2; nj++) {
                uint32_t r[4];
                ldmatrix_x4(r, b_lm + boff + nj * (16 * GSTH * 2) + kb);
                b[2 * nj][0] = r[0]; b[2 * nj][1] = r[1];
                b[2 * nj + 1][0] = r[2]; b[2 * nj + 1][1] = r[3];
            }
            #pragma unroll
            for (int mi = 0; mi < 4; mi++)
                #pragma unroll
                for (int ni = 0; ni < 4; ni++)
                    mma_f16(acc[mi][ni], a[mi], b[ni]);
        }

        buf = (buf == NSTG - 1) ? 0 : buf + 1;
        pbuf = (pbuf == NSTG - 1) ? 0 : pbuf + 1;
    }
    __syncthreads();   // protect biass reads below & uniform exit

    #pragma unroll
    for (int mi = 0; mi < 4; mi++) {
        int r0 = bm + wm + mi * 16 + gid;
        #pragma unroll
        for (int ni = 0; ni < 4; ni++) {
            int coll = wn + ni * 8 + tid4 * 2;
            int col = bn + coll;
            float v0 = acc[mi][ni][0], v1 = acc[mi][ni][1];
            float v2 = acc[mi][ni][2], v3 = acc[mi][ni][3];
            if (EPI == 1 || EPI == 2) {
                float b0 = biass[coll], b1 = biass[coll + 1];
                v0 += b0; v1 += b1; v2 += b0; v3 += b1;
                if (EPI == 1) {
                    v0 = fmaxf(v0, 0.0f); v1 = fmaxf(v1, 0.0f);
                    v2 = fmaxf(v2, 0.0f); v3 = fmaxf(v3, 0.0f);
                }
            }
            if constexpr (sizeof(OT) == 2) {
                __half2 p01, p23;
                p01.x = __float2half_rn(v0); p01.y = __float2half_rn(v1);
                p23.x = __float2half_rn(v2); p23.y = __float2half_rn(v3);
                *(__half2*)&C[(size_t)r0 * N + col] = p01;
                *(__half2*)&C[(size_t)(r0 + 8) * N + col] = p23;
            } else {
                float2 p01 = { v0, v1 };
                float2 p23 = { v2, v3 };
                *(float2*)&C[(size_t)r0 * N + col] = p01;
                *(float2*)&C[(size_t)(r0 + 8) * N + col] = p23;
            }
        }
    }
}

// ===========================================================================
__global__ void l2norm_half(const float* __restrict__ X, __half* __restrict__ Y) {
    int r = blockIdx.x;
    int t = threadIdx.x;
    const float* row = X + (size_t)r * 512;
    float a = row[t], b = row[t + 256];
    float s = a * a + b * b;
    __shared__ float sm[256];
    sm[t] = s;
    __syncthreads();
    for (int o = 128; o > 0; o >>= 1) {
        if (t < o) sm[t] += sm[t + o];
        __syncthreads();
    }
    float inv = 1.0f / sqrtf(sm[0]);
    Y[(size_t)r * 512 + t]       = __float2half_rn(a * inv);
    Y[(size_t)r * 512 + t + 256] = __float2half_rn(b * inv);
}

__global__ void l2norm_img(__half* __restrict__ Y) {
    int r = blockIdx.x;
    int t = threadIdx.x;
    float a = 0.0f, b = 0.0f;
    #pragma unroll
    for (int z = 0; z < IMG_SPLITS; z++) {
        const float* p = g_imgpart + (size_t)z * B_SZ * E_DIM + (size_t)r * 512;
        a += p[t];
        b += p[t + 256];
    }
    float s = a * a + b * b;
    __shared__ float sm[256];
    sm[t] = s;
    __syncthreads();
    for (int o = 128; o > 0; o >>= 1) {
        if (t < o) sm[t] += sm[t + o];
        __syncthreads();
    }
    float inv = 1.0f / sqrtf(sm[0]);
    Y[(size_t)r * 512 + t]       = __float2half_rn(a * inv);
    Y[(size_t)r * 512 + t + 256] = __float2half_rn(b * inv);
}

// ===========================================================================
// lse, single pass (fixed exact shift m = s; |logits| <= 1)
// ===========================================================================
__global__ void lse_kernel(const float* __restrict__ scale_ptr) {
    int r = blockIdx.x;
    int t = threadIdx.x;
    float s = scale_ptr[0];
    const float4* row4 = (const float4*)(g_logits + (size_t)r * ROWS_ALL);
    const int n4 = ROWS_ALL / 4;

    float sum = 0.0f;
    for (int j = t; j < n4; j += 256) {
        float4 v = row4[j];
        sum += expf(fmaf(s, v.x, -s)) + expf(fmaf(s, v.y, -s))
             + expf(fmaf(s, v.z, -s)) + expf(fmaf(s, v.w, -s));
    }
    __shared__ float sm[256];
    sm[t] = sum;
    __syncthreads();
    for (int o = 128; o > 0; o >>= 1) {
        if (t < o) sm[t] += sm[t + o];
        __syncthreads();
    }
    if (t == 0) {
        float diag = g_logits[(size_t)r * ROWS_ALL + r];
        g_partial[r] = fmaf(s, diag, -s) - logf(sm[0]);
    }
}

__global__ void final_kernel(float* __restrict__ out) {
    int t = threadIdx.x;
    __shared__ float sm[512];
    sm[t] = g_partial[t];
    __syncthreads();
    for (int o = 256; o > 0; o >>= 1) {
        if (t < o) sm[t] += sm[t + o];
        __syncthreads();
    }
    if (t == 0) out[0] = -sm[0] / (float)B_SZ;
}

// ===========================================================================
extern "C" void kernel_launch(void* const* d_in, const int* in_sizes, int n_in,
                              void* d_out, int out_size) {
    const float* imgs        = (const float*)d_in[0];
    const float* gps         = (const float*)d_in[1];
    const float* gallery     = (const float*)d_in[3];
    const float* W_img       = (const float*)d_in[4];
    const float* freqs       = (const float*)d_in[5];
    const float* W1          = (const float*)d_in[6];
    const float* b1          = (const float*)d_in[7];
    const float* W2          = (const float*)d_in[8];
    const float* b2          = (const float*)d_in[9];
    const float* logit_scale = (const float*)d_in[10];
    const int*   pool_idx    = (const int*)d_in[11];
    const int*   far_sel     = (const int*)d_in[12];
    const int*   perm        = (const int*)d_in[13];
    float* out = (float*)d_out;

    void *p_ffh, *p_hh, *p_emb, *p_embh, *p_imgh, *p_imgsh;
    void *p_w1t, *p_w2t, *p_wit, *p_logits, *p_part;
    cudaGetSymbolAddress(&p_ffh, g_ff_h);
    cudaGetSymbolAddress(&p_hh, g_h_h);
    cudaGetSymbolAddress(&p_emb, g_emb);
    cudaGetSymbolAddress(&p_embh, g_emb_h);
    cudaGetSymbolAddress(&p_imgh, g_img_h);
    cudaGetSymbolAddress(&p_imgsh, g_imgs_h);
    cudaGetSymbolAddress(&p_w1t, g_w1t_h);
    cudaGetSymbolAddress(&p_w2t, g_w2t_h);
    cudaGetSymbolAddress(&p_wit, g_wit_h);
    cudaGetSymbolAddress(&p_logits, g_logits);
    cudaGetSymbolAddress(&p_part, g_imgpart);
    __half* ffh  = (__half*)p_ffh;
    __half* hh   = (__half*)p_hh;
    float*  embp = (float*)p_emb;
    __half* embh = (__half*)p_embh;
    __half* imgh = (__half*)p_imgh;
    __half* w1t  = (__half*)p_w1t;
    __half* w2t  = (__half*)p_w2t;
    __half* wit  = (__half*)p_wit;
    float*  partp= (float*)p_part;

    cudaFuncSetAttribute(gemm_h<0, float>,  cudaFuncAttributeMaxDynamicSharedMemorySize, GEMM_SMEM);
    cudaFuncSetAttribute(gemm_h<1, __half>, cudaFuncAttributeMaxDynamicSharedMemorySize, GEMM_SMEM);
    cudaFuncSetAttribute(gemm_h<2, float>,  cudaFuncAttributeMaxDynamicSharedMemorySize, GEMM_SMEM);

    select_kernel<<<B_SZ, 192>>>(gps, gallery, pool_idx, far_sel, perm);
    ff_kernel<<<ROWS_ALL, 256>>>(freqs);
    prep_kernel<<<3072, 256>>>(W1, W2, W_img, imgs);

    // h = relu(ff @ W1 + b1) -> fp16     K=512
    gemm_h<1, __half><<<dim3(H_DIM / 128, ROWS_ALL / 128, 1), 256, GEMM_SMEM>>>(
        ffh, w1t, hh, b1, ROWS_ALL, H_DIM, 2 * F_DIM, 2 * F_DIM, 2 * F_DIM);
    // emb = h @ W2 + b2 -> f32           K=1024
    gemm_h<2, float><<<dim3(E_DIM / 128, ROWS_ALL / 128, 1), 256, GEMM_SMEM>>>(
        hh, w2t, embp, b2, ROWS_ALL, E_DIM, H_DIM, H_DIM, H_DIM);
    l2norm_half<<<ROWS_ALL, 256>>>(embp, embh);

    // img_emb partials: split-K x8       K=256 each
    gemm_h<0, float><<<dim3(E_DIM / 128, B_SZ / 128, IMG_SPLITS), 256, GEMM_SMEM>>>(
        (__half*)p_imgsh, wit, partp, nullptr, B_SZ, E_DIM, D_IMG / IMG_SPLITS, D_IMG, D_IMG);
    l2norm_img<<<B_SZ, 256>>>(imgh);

    // logits = img_emb @ emb^T -> f32    K=512
    gemm_h<0, float><<<dim3(ROWS_ALL / 128, B_SZ / 128, 1), 256, GEMM_SMEM>>>(
        imgh, embh, (float*)p_logits, nullptr, B_SZ, ROWS_ALL, E_DIM, E_DIM, E_DIM);

    lse_kernel<<<B_SZ, 256>>>(logit_scale);
    final_kernel<<<1, B_SZ>>>(out);
}